// round 12
// baseline (speedup 1.0000x reference)
#include <cuda_runtime.h>
#include <math.h>

#define NT   512
#define TILE 128
#define HID  128
#define RS   132   // lane-stride 132 floats -> 4-bank quads tile all 32 banks

// shared-memory float offsets
#define OFF_W2   0        // 16384  W2[j][k] row-major
#define OFF_H1   16384    // 16896  h1row[s][j] stride RS    -> ends 33280
#define OFF_G2   33280    // 16896  g2row[s][k] stride RS    -> ends 50176
#define OFF_W1T  50176    // 512    W1T[j][i]
#define OFF_B1   50688    // 128
#define OFF_B2   50816    // 128
#define OFF_W3   50944    // 128
#define OFF_FT   51072    // 512    feat[s][4]
#define OFF_XD   51584    // 256    qd[s][2]
#define OFF_PF   OFF_G2   // per-half 4096-float gfeat partials overlay own G2 rows
#define SMEM_FLOATS 51840 // 207360 bytes

typedef unsigned long long ull;
union F4U2 { float4 f4; ull u[2]; };

__device__ __forceinline__ void ffma2(ull& acc, ull a, ull b) {
    asm("fma.rn.f32x2 %0, %1, %2, %0;" : "+l"(acc) : "l"(a), "l"(b));
}
__device__ __forceinline__ ull pack2(float lo, float hi) {
    ull r; asm("mov.b64 %0, {%1, %2};" : "=l"(r) : "f"(lo), "f"(hi)); return r;
}
__device__ __forceinline__ void unpack2(ull v, float& lo, float& hi) {
    asm("mov.b64 {%0, %1}, %2;" : "=f"(lo), "=f"(hi) : "l"(v));
}
__device__ __forceinline__ float tanh_hw(float x) {
    float r;
    asm("tanh.approx.f32 %0, %1;" : "=f"(r) : "f"(x));
    return r;
}
__device__ __forceinline__ void half_bar(int id) {
    asm volatile("bar.sync %0, 256;" :: "r"(id) : "memory");
}

__global__ __launch_bounds__(NT, 1)
void lnn_kernel(const float* __restrict__ X,
                const float* __restrict__ W1, const float* __restrict__ b1,
                const float* __restrict__ W2, const float* __restrict__ b2,
                const float* __restrict__ W3,
                float* __restrict__ out, int B)
{
    extern __shared__ float sm[];
    const int tid  = threadIdx.x;
    const int base = blockIdx.x * TILE;
    const int lane = tid & 31;
    const int half = tid >> 8;          // 0 or 1: independent 256-thread team
    const int t    = tid & 255;         // id within team
    const int hb   = half * 64;         // team's sample base (block-local)
    const int bid  = 1 + half;          // named barrier id

    // ---------------- Phase 0: stage (full block, one __syncthreads) ------
    if (tid < TILE) {
        int gs = base + tid;
        float4 x = make_float4(0.f, 0.f, 0.f, 0.f);
        if (gs < B) x = *(const float4*)&X[gs * 4];
        float s1, c1, s2, c2;
        sincosf(x.x, &s1, &c1);
        sincosf(x.y, &s2, &c2);
        sm[OFF_FT + tid * 4 + 0] = s1;
        sm[OFF_FT + tid * 4 + 1] = c1;
        sm[OFF_FT + tid * 4 + 2] = s2;
        sm[OFF_FT + tid * 4 + 3] = c2;
        sm[OFF_XD + tid * 2 + 0] = x.z;
        sm[OFF_XD + tid * 2 + 1] = x.w;
    } else {
        int tt = tid - TILE;                      // 0..383
        const float4* W2v = (const float4*)W2;
        for (int i = tt; i < HID * HID / 4; i += NT - TILE)
            *(float4*)&sm[OFF_W2 + i * 4] = W2v[i];
        for (int i = tt; i < 4 * HID; i += NT - TILE) {
            int r = i >> 7, j = i & 127;          // W1 is [4][128]
            sm[OFF_W1T + j * 4 + r] = W1[i];
        }
        for (int i = tt; i < HID; i += NT - TILE) {
            sm[OFF_B1 + i] = b1[i];
            sm[OFF_B2 + i] = b2[i];
            sm[OFF_W3 + i] = W3[i];
        }
    }
    __syncthreads();

    // team-local work mapping: 4 samples x 8 outputs per thread
    const int og8 = (t >> 4) * 8;       // 16 output groups (k0 / j0), half-warp uniform
    const int sl  = lane & 15;          // sample slot; samples hb + sl + 16u

    // ---------------- Phase A: h1row[s][j] = tanh(b1 + feat.W1T) ----------
    {
        const int s  = hb + (t & 63);
        const int j0 = (t >> 6) * 32;             // 4 groups x 32 j
        float4 f = *(const float4*)&sm[OFF_FT + s * 4];
        #pragma unroll
        for (int c = 0; c < 32; c += 4) {
            float hv[4];
            #pragma unroll
            for (int q = 0; q < 4; q++) {
                int j = j0 + c + q;
                float4 w = *(const float4*)&sm[OFF_W1T + j * 4];
                float z = sm[OFF_B1 + j] + f.x*w.x + f.y*w.y + f.z*w.z + f.w*w.w;
                hv[q] = tanh_hw(z);
            }
            *(float4*)&sm[OFF_H1 + s * RS + j0 + c]
                = make_float4(hv[0], hv[1], hv[2], hv[3]);
        }
    }
    half_bar(bid);

    // ---------------- Phase B: z2 = h1@W2 (+b2); g2 = W3*sech^2 -----------
    {
        const int k0 = og8;
        ull acc[4][4];
        #pragma unroll
        for (int m = 0; m < 4; m++) {
            ull bp = pack2(sm[OFF_B2 + k0 + 2*m], sm[OFF_B2 + k0 + 2*m + 1]);
            acc[0][m] = bp; acc[1][m] = bp; acc[2][m] = bp; acc[3][m] = bp;
        }
        #pragma unroll 4
        for (int j = 0; j < HID; j += 4) {
            float hv[4][4];
            #pragma unroll
            for (int u = 0; u < 4; u++) {
                float4 h = *(const float4*)&sm[OFF_H1 + (hb + sl + 16*u) * RS + j];
                hv[u][0] = h.x; hv[u][1] = h.y; hv[u][2] = h.z; hv[u][3] = h.w;
            }
            #pragma unroll
            for (int q = 0; q < 4; q++) {
                F4U2 wlo, whi;
                wlo.f4 = *(const float4*)&sm[OFF_W2 + (j + q) * HID + k0];
                whi.f4 = *(const float4*)&sm[OFF_W2 + (j + q) * HID + k0 + 4];
                #pragma unroll
                for (int u = 0; u < 4; u++) {
                    ull hp = pack2(hv[u][q], hv[u][q]);
                    ffma2(acc[u][0], hp, wlo.u[0]);
                    ffma2(acc[u][1], hp, wlo.u[1]);
                    ffma2(acc[u][2], hp, whi.u[0]);
                    ffma2(acc[u][3], hp, whi.u[1]);
                }
            }
        }
        #pragma unroll
        for (int u = 0; u < 4; u++) {
            int s = hb + sl + 16*u;
            float g[8];
            #pragma unroll
            for (int m = 0; m < 4; m++) {
                float z0, z1;
                unpack2(acc[u][m], z0, z1);
                float t0 = tanh_hw(z0), t1 = tanh_hw(z1);
                g[2*m]     = sm[OFF_W3 + k0 + 2*m]     * (1.0f - t0 * t0);
                g[2*m + 1] = sm[OFF_W3 + k0 + 2*m + 1] * (1.0f - t1 * t1);
            }
            *(float4*)&sm[OFF_G2 + s * RS + k0]     = make_float4(g[0], g[1], g[2], g[3]);
            *(float4*)&sm[OFF_G2 + s * RS + k0 + 4] = make_float4(g[4], g[5], g[6], g[7]);
        }
    }
    half_bar(bid);

    // ---------------- Phase C: a = g2@W2^T (k-dot); g1; gfeat partials ----
    float pf[4][4];
    {
        const int j0 = og8;
        ull acc[4][8];
        #pragma unroll
        for (int u = 0; u < 4; u++)
            #pragma unroll
            for (int jj = 0; jj < 8; jj++) acc[u][jj] = 0ull;

        #pragma unroll 2
        for (int k = 0; k < HID; k += 4) {
            F4U2 g[4];
            #pragma unroll
            for (int u = 0; u < 4; u++)
                g[u].f4 = *(const float4*)&sm[OFF_G2 + (hb + sl + 16*u) * RS + k];
            #pragma unroll
            for (int jj = 0; jj < 8; jj++) {
                F4U2 w; w.f4 = *(const float4*)&sm[OFF_W2 + (j0 + jj) * HID + k];
                #pragma unroll
                for (int u = 0; u < 4; u++) {
                    ffma2(acc[u][jj], g[u].u[0], w.u[0]);
                    ffma2(acc[u][jj], g[u].u[1], w.u[1]);
                }
            }
        }
        #pragma unroll
        for (int u = 0; u < 4; u++) {
            int s = hb + sl + 16*u;
            float4 h0  = *(const float4*)&sm[OFF_H1 + s * RS + j0];
            float4 h1v = *(const float4*)&sm[OFF_H1 + s * RS + j0 + 4];
            float hh[8] = {h0.x, h0.y, h0.z, h0.w, h1v.x, h1v.y, h1v.z, h1v.w};
            float gf0 = 0.f, gf1 = 0.f, gf2 = 0.f, gf3 = 0.f;
            #pragma unroll
            for (int jj = 0; jj < 8; jj++) {
                float lo, hi;
                unpack2(acc[u][jj], lo, hi);
                float a = lo + hi;
                float g1v = a * (1.0f - hh[jj] * hh[jj]);
                float4 w = *(const float4*)&sm[OFF_W1T + (j0 + jj) * 4];
                gf0 = fmaf(g1v, w.x, gf0);
                gf1 = fmaf(g1v, w.y, gf1);
                gf2 = fmaf(g1v, w.z, gf2);
                gf3 = fmaf(g1v, w.w, gf3);
            }
            pf[u][0] = gf0; pf[u][1] = gf1; pf[u][2] = gf2; pf[u][3] = gf3;
        }
    }
    half_bar(bid);   // team's G2 reads done -> PF may overlay own G2 rows

    {
        const int pfb = OFF_PF + half * 8448;     // own half's dead G2 rows
        const int jg  = t >> 4;                   // 16 j-groups
        #pragma unroll
        for (int u = 0; u < 4; u++)
            *(float4*)&sm[pfb + (jg * 64 + sl + 16*u) * 4]
                = make_float4(pf[u][0], pf[u][1], pf[u][2], pf[u][3]);
    }
    half_bar(bid);

    // ---------------- Reduce partials + analytic dynamics + output --------
    if (t < 64) {
        const int pfb = OFF_PF + half * 8448;
        const int s   = hb + t;
        float gf0 = 0.f, gf1 = 0.f, gf2 = 0.f, gf3 = 0.f;
        #pragma unroll
        for (int jg = 0; jg < 16; jg++) {
            float4 p = *(const float4*)&sm[pfb + (jg * 64 + t) * 4];
            gf0 += p.x; gf1 += p.y; gf2 += p.z; gf3 += p.w;
        }

        float w1 = sm[OFF_XD + s * 2 + 0];
        float w2 = sm[OFF_XD + s * 2 + 1];
        float s1 = sm[OFF_FT + s * 4 + 0];
        float c1 = sm[OFF_FT + s * 4 + 1];
        float s2 = sm[OFF_FT + s * 4 + 2];
        float c2 = sm[OFF_FT + s * 4 + 3];

        float sd = s1 * c2 - c1 * s2;      // sin(t1 - t2)
        float cd = c1 * c2 + s1 * s2;      // cos(t1 - t2)

        float dV1 = gf0 * c1 - gf1 * s1;
        float dV2 = gf2 * c2 - gf3 * s2;

        float tt  = w1 * w2 * sd;
        float dL1 = -tt - dV1;
        float dL2 =  tt - dV2;

        float cc = sd * (w2 - w1);
        float r1 = dL1 - w2 * cc;
        float r2 = dL2 - w1 * cc;

        float det  = 2.0f - cd * cd;
        float rdet = __fdividef(1.0f, det);
        float qdd1 = (r1 - cd * r2) * rdet;
        float qdd2 = (2.0f * r2 - cd * r1) * rdet;

        int gs = base + s;
        if (gs < B)
            *(float4*)&out[gs * 4] = make_float4(w1, w2, qdd1, qdd2);
    }
}

extern "C" void kernel_launch(void* const* d_in, const int* in_sizes, int n_in,
                              void* d_out, int out_size)
{
    const float* X  = (const float*)d_in[0];
    const float* W1 = (const float*)d_in[1];
    const float* b1 = (const float*)d_in[2];
    const float* W2 = (const float*)d_in[3];
    const float* b2 = (const float*)d_in[4];
    const float* W3 = (const float*)d_in[5];
    // d_in[6] = b3: no effect on grad(V) -> unused
    float* out = (float*)d_out;

    int B = in_sizes[0] / 4;
    size_t smem = SMEM_FLOATS * sizeof(float);
    cudaFuncSetAttribute(lnn_kernel, cudaFuncAttributeMaxDynamicSharedMemorySize,
                         (int)smem);
    int grid = (B + TILE - 1) / TILE;
    lnn_kernel<<<grid, NT, smem>>>(X, W1, b1, W2, b2, W3, out, B);
}

// round 13
// speedup vs baseline: 1.6866x; 1.6866x over previous
#include <cuda_runtime.h>
#include <math.h>

#define NT   512
#define TILE 128
#define HID  128
#define RS   132   // lane-stride 132 floats -> 4-bank quads tile all 32 banks

// shared-memory float offsets (R11 layout)
#define OFF_W2   0        // 16384  W2[j][k] row-major
#define OFF_H1   16384    // 16896  h1row[s][j] stride RS    -> ends 33280
#define OFF_G2   33280    // 16896  g2row[s][k] stride RS    -> ends 50176
#define OFF_W1T  50176    // 512    W1T[j][i]
#define OFF_B1   50688    // 128
#define OFF_B2   50816    // 128
#define OFF_W3   50944    // 128
#define OFF_FT   51072    // 512    feat[s][4]
#define OFF_XD   51584    // 256    qd[s][2]
#define OFF_GF   51840    // 512    reduced gfeat [s][4]
#define OFF_PF   OFF_G2   // 8192   gfeat partials [jg][s][4] overlay G2 (dead)
#define SMEM_FLOATS 52352 // 209408 bytes

typedef unsigned long long ull;
union F4U2 { float4 f4; ull u[2]; };

__device__ __forceinline__ void ffma2(ull& acc, ull a, ull b) {
    asm("fma.rn.f32x2 %0, %1, %2, %0;" : "+l"(acc) : "l"(a), "l"(b));
}
__device__ __forceinline__ ull pack2(float lo, float hi) {
    ull r; asm("mov.b64 %0, {%1, %2};" : "=l"(r) : "f"(lo), "f"(hi)); return r;
}
__device__ __forceinline__ void unpack2(ull v, float& lo, float& hi) {
    asm("mov.b64 {%0, %1}, %2;" : "=f"(lo), "=f"(hi) : "l"(v));
}
__device__ __forceinline__ float tanh_hw(float x) {
    float r;
    asm("tanh.approx.f32 %0, %1;" : "=f"(r) : "f"(x));
    return r;
}

__global__ __launch_bounds__(NT, 1)
void lnn_kernel(const float* __restrict__ X,
                const float* __restrict__ W1, const float* __restrict__ b1,
                const float* __restrict__ W2, const float* __restrict__ b2,
                const float* __restrict__ W3,
                float* __restrict__ out, int B, int ntiles)
{
    extern __shared__ float sm[];
    const int tid  = threadIdx.x;
    const int lane = tid & 31;

    // ---------------- One-time staging: weights + biases ------------------
    {
        const float4* W2v = (const float4*)W2;
        for (int i = tid; i < HID * HID / 4; i += NT)
            *(float4*)&sm[OFF_W2 + i * 4] = W2v[i];
        if (tid < 4 * HID) {
            int r = tid >> 7, j = tid & 127;      // W1 is [4][128]
            sm[OFF_W1T + j * 4 + r] = W1[tid];
        }
        if (tid < HID) {
            sm[OFF_B1 + tid] = b1[tid];
            sm[OFF_B2 + tid] = b2[tid];
            sm[OFF_W3 + tid] = W3[tid];
        }
    }

    const int og8 = (tid >> 5) * 8;    // warp-uniform output group (k0 / j0)

    // ---------------- Persistent loop over tiles --------------------------
    for (int tile = blockIdx.x; tile < ntiles; tile += gridDim.x) {
        const int base = tile * TILE;

        // ---- per-tile staging: X -> feat/qd (128 threads) ----
        __syncthreads();               // FT/XD free (prev tile done / first entry)
        if (tid < TILE) {
            int gs = base + tid;
            float4 x = make_float4(0.f, 0.f, 0.f, 0.f);
            if (gs < B) x = *(const float4*)&X[gs * 4];
            float s1, c1, s2, c2;
            sincosf(x.x, &s1, &c1);
            sincosf(x.y, &s2, &c2);
            sm[OFF_FT + tid * 4 + 0] = s1;
            sm[OFF_FT + tid * 4 + 1] = c1;
            sm[OFF_FT + tid * 4 + 2] = s2;
            sm[OFF_FT + tid * 4 + 3] = c2;
            sm[OFF_XD + tid * 2 + 0] = x.z;
            sm[OFF_XD + tid * 2 + 1] = x.w;
        }
        __syncthreads();

        // ---- Phase A: h1row[s][j] = tanh(b1 + feat.W1T) ----
        {
            const int s  = tid & 127;
            const int j0 = (tid >> 7) * 32;
            float4 f = *(const float4*)&sm[OFF_FT + s * 4];
            #pragma unroll
            for (int c = 0; c < 32; c += 4) {
                float hv[4];
                #pragma unroll
                for (int q = 0; q < 4; q++) {
                    int j = j0 + c + q;
                    float4 w = *(const float4*)&sm[OFF_W1T + j * 4];
                    float z = sm[OFF_B1 + j] + f.x*w.x + f.y*w.y + f.z*w.z + f.w*w.w;
                    hv[q] = tanh_hw(z);
                }
                *(float4*)&sm[OFF_H1 + s * RS + j0 + c]
                    = make_float4(hv[0], hv[1], hv[2], hv[3]);
            }
        }
        __syncthreads();

        // ---- Phase B: z2 = h1@W2 (+b2); g2 = W3*sech^2 ----
        {
            const int k0 = og8;
            ull acc[4][4];
            #pragma unroll
            for (int m = 0; m < 4; m++) {
                ull bp = pack2(sm[OFF_B2 + k0 + 2*m], sm[OFF_B2 + k0 + 2*m + 1]);
                acc[0][m] = bp; acc[1][m] = bp; acc[2][m] = bp; acc[3][m] = bp;
            }
            #pragma unroll 4
            for (int j = 0; j < HID; j += 4) {
                float hv[4][4];
                #pragma unroll
                for (int u = 0; u < 4; u++) {
                    float4 h = *(const float4*)&sm[OFF_H1 + (lane + 32 * u) * RS + j];
                    hv[u][0] = h.x; hv[u][1] = h.y; hv[u][2] = h.z; hv[u][3] = h.w;
                }
                #pragma unroll
                for (int q = 0; q < 4; q++) {
                    F4U2 wlo, whi;
                    wlo.f4 = *(const float4*)&sm[OFF_W2 + (j + q) * HID + k0];
                    whi.f4 = *(const float4*)&sm[OFF_W2 + (j + q) * HID + k0 + 4];
                    #pragma unroll
                    for (int u = 0; u < 4; u++) {
                        ull hp = pack2(hv[u][q], hv[u][q]);
                        ffma2(acc[u][0], hp, wlo.u[0]);
                        ffma2(acc[u][1], hp, wlo.u[1]);
                        ffma2(acc[u][2], hp, whi.u[0]);
                        ffma2(acc[u][3], hp, whi.u[1]);
                    }
                }
            }
            #pragma unroll
            for (int u = 0; u < 4; u++) {
                int s = lane + 32 * u;
                float g[8];
                #pragma unroll
                for (int m = 0; m < 4; m++) {
                    float z0, z1;
                    unpack2(acc[u][m], z0, z1);
                    float t0 = tanh_hw(z0), t1 = tanh_hw(z1);
                    g[2*m]     = sm[OFF_W3 + k0 + 2*m]     * (1.0f - t0 * t0);
                    g[2*m + 1] = sm[OFF_W3 + k0 + 2*m + 1] * (1.0f - t1 * t1);
                }
                *(float4*)&sm[OFF_G2 + s * RS + k0]     = make_float4(g[0], g[1], g[2], g[3]);
                *(float4*)&sm[OFF_G2 + s * RS + k0 + 4] = make_float4(g[4], g[5], g[6], g[7]);
            }
        }
        __syncthreads();

        // ---- Phase C: a = g2@W2^T (k-dot); g1; gfeat partials ----
        float pf[4][4];
        {
            const int j0 = og8;
            ull acc[4][8];
            #pragma unroll
            for (int u = 0; u < 4; u++)
                #pragma unroll
                for (int jj = 0; jj < 8; jj++) acc[u][jj] = 0ull;

            #pragma unroll 2
            for (int k = 0; k < HID; k += 4) {
                F4U2 g[4];
                #pragma unroll
                for (int u = 0; u < 4; u++)
                    g[u].f4 = *(const float4*)&sm[OFF_G2 + (lane + 32 * u) * RS + k];
                #pragma unroll
                for (int jj = 0; jj < 8; jj++) {
                    F4U2 w; w.f4 = *(const float4*)&sm[OFF_W2 + (j0 + jj) * HID + k];
                    #pragma unroll
                    for (int u = 0; u < 4; u++) {
                        ffma2(acc[u][jj], g[u].u[0], w.u[0]);
                        ffma2(acc[u][jj], g[u].u[1], w.u[1]);
                    }
                }
            }
            #pragma unroll
            for (int u = 0; u < 4; u++) {
                int s = lane + 32 * u;
                float4 h0  = *(const float4*)&sm[OFF_H1 + s * RS + j0];
                float4 h1v = *(const float4*)&sm[OFF_H1 + s * RS + j0 + 4];
                float hh[8] = {h0.x, h0.y, h0.z, h0.w, h1v.x, h1v.y, h1v.z, h1v.w};
                float gf0 = 0.f, gf1 = 0.f, gf2 = 0.f, gf3 = 0.f;
                #pragma unroll
                for (int jj = 0; jj < 8; jj++) {
                    float lo, hi;
                    unpack2(acc[u][jj], lo, hi);
                    float a = lo + hi;
                    float g1v = a * (1.0f - hh[jj] * hh[jj]);
                    float4 w = *(const float4*)&sm[OFF_W1T + (j0 + jj) * 4];
                    gf0 = fmaf(g1v, w.x, gf0);
                    gf1 = fmaf(g1v, w.y, gf1);
                    gf2 = fmaf(g1v, w.z, gf2);
                    gf3 = fmaf(g1v, w.w, gf3);
                }
                pf[u][0] = gf0; pf[u][1] = gf1; pf[u][2] = gf2; pf[u][3] = gf3;
            }
        }
        __syncthreads();   // all G2 reads done -> PF may overlay G2

        {
            const int jg = tid >> 5;   // 16 j-groups
            #pragma unroll
            for (int u = 0; u < 4; u++)
                *(float4*)&sm[OFF_PF + (jg * 128 + lane + 32 * u) * 4]
                    = make_float4(pf[u][0], pf[u][1], pf[u][2], pf[u][3]);
        }
        __syncthreads();

        // ---- Reduce gfeat partials over the 16 j-groups ----
        {
            int rs = tid >> 2, c = tid & 3;      // 128 s x 4 comps
            float a = 0.f;
            #pragma unroll
            for (int jg = 0; jg < 16; jg++)
                a += sm[OFF_PF + (jg * 128 + rs) * 4 + c];
            sm[OFF_GF + rs * 4 + c] = a;
        }
        __syncthreads();

        // ---- Final: analytic dynamics + output ----
        if (tid < TILE) {
            float4 gf = *(const float4*)&sm[OFF_GF + tid * 4];

            float w1 = sm[OFF_XD + tid * 2 + 0];
            float w2 = sm[OFF_XD + tid * 2 + 1];
            float s1 = sm[OFF_FT + tid * 4 + 0];
            float c1 = sm[OFF_FT + tid * 4 + 1];
            float s2 = sm[OFF_FT + tid * 4 + 2];
            float c2 = sm[OFF_FT + tid * 4 + 3];

            float sd = s1 * c2 - c1 * s2;      // sin(t1 - t2)
            float cd = c1 * c2 + s1 * s2;      // cos(t1 - t2)

            float dV1 = gf.x * c1 - gf.y * s1;
            float dV2 = gf.z * c2 - gf.w * s2;

            float tt  = w1 * w2 * sd;
            float dL1 = -tt - dV1;
            float dL2 =  tt - dV2;

            float cc = sd * (w2 - w1);
            float r1 = dL1 - w2 * cc;
            float r2 = dL2 - w1 * cc;

            float det  = 2.0f - cd * cd;
            float rdet = __fdividef(1.0f, det);
            float qdd1 = (r1 - cd * r2) * rdet;
            float qdd2 = (2.0f * r2 - cd * r1) * rdet;

            int gs = base + tid;
            if (gs < B)
                *(float4*)&out[gs * 4] = make_float4(w1, w2, qdd1, qdd2);
        }
    }
}

extern "C" void kernel_launch(void* const* d_in, const int* in_sizes, int n_in,
                              void* d_out, int out_size)
{
    const float* X  = (const float*)d_in[0];
    const float* W1 = (const float*)d_in[1];
    const float* b1 = (const float*)d_in[2];
    const float* W2 = (const float*)d_in[3];
    const float* b2 = (const float*)d_in[4];
    const float* W3 = (const float*)d_in[5];
    // d_in[6] = b3: no effect on grad(V) -> unused
    float* out = (float*)d_out;

    int B = in_sizes[0] / 4;
    int ntiles = (B + TILE - 1) / TILE;

    int nsm = 148;
    cudaDeviceGetAttribute(&nsm, cudaDevAttrMultiProcessorCount, 0);
    int grid = ntiles < nsm ? ntiles : nsm;

    size_t smem = SMEM_FLOATS * sizeof(float);
    cudaFuncSetAttribute(lnn_kernel, cudaFuncAttributeMaxDynamicSharedMemorySize,
                         (int)smem);
    lnn_kernel<<<grid, NT, smem>>>(X, W1, b1, W2, b2, W3, out, B, ntiles);
}

// round 15
// speedup vs baseline: 1.7112x; 1.0146x over previous
#include <cuda_runtime.h>
#include <math.h>
#include <stdint.h>

#define NT   512
#define TILE 128
#define HID  128
#define RS   132   // lane-stride 132 floats -> 4-bank quads tile all 32 banks

// shared-memory float offsets
#define OFF_W2   0        // 16384  W2[j][k] row-major
#define OFF_H1   16384    // 16896  h1row[s][j] stride RS    -> ends 33280
#define OFF_G2   33280    // 16896  g2row[s][k] stride RS    -> ends 50176
#define OFF_W1T  50176    // 512    W1T[j][i]
#define OFF_B1   50688    // 128
#define OFF_B2   50816    // 128
#define OFF_W3   50944    // 128
#define OFF_FT   51072    // 512    feat[s][4]
#define OFF_XD   51584    // 256    qd[s][2]
#define OFF_XB   51840    // 512    X prefetch buffer [s][4]
#define OFF_PF   OFF_G2   // 8192   gfeat partials [jg][s][4] overlay G2 (dead)
#define SMEM_FLOATS 52352 // 209408 bytes

typedef unsigned long long ull;
union F4U2 { float4 f4; ull u[2]; };

__device__ __forceinline__ void ffma2(ull& acc, ull a, ull b) {
    asm("fma.rn.f32x2 %0, %1, %2, %0;" : "+l"(acc) : "l"(a), "l"(b));
}
__device__ __forceinline__ ull pack2(float lo, float hi) {
    ull r; asm("mov.b64 %0, {%1, %2};" : "=l"(r) : "f"(lo), "f"(hi)); return r;
}
__device__ __forceinline__ void unpack2(ull v, float& lo, float& hi) {
    asm("mov.b64 {%0, %1}, %2;" : "=f"(lo), "=f"(hi) : "l"(v));
}
__device__ __forceinline__ float tanh_hw(float x) {
    float r;
    asm("tanh.approx.f32 %0, %1;" : "=f"(r) : "f"(x));
    return r;
}
__device__ __forceinline__ uint32_t smem_u32(const void* p) {
    uint32_t a;
    asm("{ .reg .u64 t; cvta.to.shared.u64 t, %1; cvt.u32.u64 %0, t; }"
        : "=r"(a) : "l"(p));
    return a;
}
__device__ __forceinline__ void cp_async16(uint32_t dst, const void* src) {
    asm volatile("cp.async.ca.shared.global [%0], [%1], 16;"
                 :: "r"(dst), "l"(src) : "memory");
}

__global__ __launch_bounds__(NT, 1)
void lnn_kernel(const float* __restrict__ X,
                const float* __restrict__ W1, const float* __restrict__ b1,
                const float* __restrict__ W2, const float* __restrict__ b2,
                const float* __restrict__ W3,
                float* __restrict__ out, int B, int ntiles)
{
    extern __shared__ float sm[];
    const int tid  = threadIdx.x;
    const int lane = tid & 31;
    const uint32_t xb_addr = smem_u32(&sm[OFF_XB]);

    // ---------------- One-time staging: weights + biases + first X --------
    {
        const float4* W2v = (const float4*)W2;
        for (int i = tid; i < HID * HID / 4; i += NT)
            *(float4*)&sm[OFF_W2 + i * 4] = W2v[i];
        if (tid < 4 * HID) {
            int r = tid >> 7, j = tid & 127;      // W1 is [4][128]
            sm[OFF_W1T + j * 4 + r] = W1[tid];
        }
        if (tid < HID) {
            sm[OFF_B1 + tid] = b1[tid];
            sm[OFF_B2 + tid] = b2[tid];
            sm[OFF_W3 + tid] = W3[tid];
        }
        if (tid < TILE) {
            int gs = blockIdx.x * TILE + tid;
            if (gs < B)
                cp_async16(xb_addr + tid * 16, &X[gs * 4]);
            else
                *(float4*)&sm[OFF_XB + tid * 4] = make_float4(0.f, 0.f, 0.f, 0.f);
            asm volatile("cp.async.commit_group;");
        }
    }

    const int og8 = (tid >> 5) * 8;    // warp-uniform output group (k0 / j0)

    // ---------------- Persistent loop over tiles --------------------------
    for (int tile = blockIdx.x; tile < ntiles; tile += gridDim.x) {
        const int base = tile * TILE;

        if (tid < TILE) asm volatile("cp.async.wait_group 0;" ::: "memory");
        __syncthreads();               // XBUF ready; FT/XD free

        // ---- staging: XBUF -> feat/qd (256 threads, split by angle) ----
        if (tid < 256) {
            int s = tid & 127;
            float4 x = *(const float4*)&sm[OFF_XB + s * 4];
            if (tid < 128) {
                float s1, c1;
                sincosf(x.x, &s1, &c1);
                sm[OFF_FT + s * 4 + 0] = s1;
                sm[OFF_FT + s * 4 + 1] = c1;
                sm[OFF_XD + s * 2 + 0] = x.z;
                sm[OFF_XD + s * 2 + 1] = x.w;
            } else {
                float s2, c2;
                sincosf(x.y, &s2, &c2);
                sm[OFF_FT + s * 4 + 2] = s2;
                sm[OFF_FT + s * 4 + 3] = c2;
            }
        }
        __syncthreads();

        // ---- prefetch next tile's X (hidden under GEMM phases) ----
        {
            int nt2 = tile + gridDim.x;
            if (nt2 < ntiles && tid < TILE) {
                int gs = nt2 * TILE + tid;
                if (gs < B)
                    cp_async16(xb_addr + tid * 16, &X[gs * 4]);
                else
                    *(float4*)&sm[OFF_XB + tid * 4] = make_float4(0.f, 0.f, 0.f, 0.f);
                asm volatile("cp.async.commit_group;");
            }
        }

        // ---- Phase A: h1row[s][j] = tanh(b1 + feat.W1T) ----
        {
            const int s  = tid & 127;
            const int j0 = (tid >> 7) * 32;
            float4 f = *(const float4*)&sm[OFF_FT + s * 4];
            #pragma unroll
            for (int c = 0; c < 32; c += 4) {
                float hv[4];
                #pragma unroll
                for (int q = 0; q < 4; q++) {
                    int j = j0 + c + q;
                    float4 w = *(const float4*)&sm[OFF_W1T + j * 4];
                    float z = sm[OFF_B1 + j] + f.x*w.x + f.y*w.y + f.z*w.z + f.w*w.w;
                    hv[q] = tanh_hw(z);
                }
                *(float4*)&sm[OFF_H1 + s * RS + j0 + c]
                    = make_float4(hv[0], hv[1], hv[2], hv[3]);
            }
        }
        __syncthreads();

        // ---- Phase B: z2 = h1@W2 (+b2); g2 = W3*sech^2 ----
        {
            const int k0 = og8;
            ull acc[4][4];
            #pragma unroll
            for (int m = 0; m < 4; m++) {
                ull bp = pack2(sm[OFF_B2 + k0 + 2*m], sm[OFF_B2 + k0 + 2*m + 1]);
                acc[0][m] = bp; acc[1][m] = bp; acc[2][m] = bp; acc[3][m] = bp;
            }
            #pragma unroll 4
            for (int j = 0; j < HID; j += 4) {
                float hv[4][4];
                #pragma unroll
                for (int u = 0; u < 4; u++) {
                    float4 h = *(const float4*)&sm[OFF_H1 + (lane + 32 * u) * RS + j];
                    hv[u][0] = h.x; hv[u][1] = h.y; hv[u][2] = h.z; hv[u][3] = h.w;
                }
                #pragma unroll
                for (int q = 0; q < 4; q++) {
                    F4U2 wlo, whi;
                    wlo.f4 = *(const float4*)&sm[OFF_W2 + (j + q) * HID + k0];
                    whi.f4 = *(const float4*)&sm[OFF_W2 + (j + q) * HID + k0 + 4];
                    #pragma unroll
                    for (int u = 0; u < 4; u++) {
                        ull hp = pack2(hv[u][q], hv[u][q]);
                        ffma2(acc[u][0], hp, wlo.u[0]);
                        ffma2(acc[u][1], hp, wlo.u[1]);
                        ffma2(acc[u][2], hp, whi.u[0]);
                        ffma2(acc[u][3], hp, whi.u[1]);
                    }
                }
            }
            #pragma unroll
            for (int u = 0; u < 4; u++) {
                int s = lane + 32 * u;
                float g[8];
                #pragma unroll
                for (int m = 0; m < 4; m++) {
                    float z0, z1;
                    unpack2(acc[u][m], z0, z1);
                    float t0 = tanh_hw(z0), t1 = tanh_hw(z1);
                    g[2*m]     = sm[OFF_W3 + k0 + 2*m]     * (1.0f - t0 * t0);
                    g[2*m + 1] = sm[OFF_W3 + k0 + 2*m + 1] * (1.0f - t1 * t1);
                }
                *(float4*)&sm[OFF_G2 + s * RS + k0]     = make_float4(g[0], g[1], g[2], g[3]);
                *(float4*)&sm[OFF_G2 + s * RS + k0 + 4] = make_float4(g[4], g[5], g[6], g[7]);
            }
        }
        __syncthreads();

        // ---- Phase C: a = g2@W2^T (k-dot); g1; gfeat partials ----
        float pf[4][4];
        {
            const int j0 = og8;
            ull acc[4][8];
            #pragma unroll
            for (int u = 0; u < 4; u++)
                #pragma unroll
                for (int jj = 0; jj < 8; jj++) acc[u][jj] = 0ull;

            #pragma unroll 2
            for (int k = 0; k < HID; k += 4) {
                F4U2 g[4];
                #pragma unroll
                for (int u = 0; u < 4; u++)
                    g[u].f4 = *(const float4*)&sm[OFF_G2 + (lane + 32 * u) * RS + k];
                #pragma unroll
                for (int jj = 0; jj < 8; jj++) {
                    F4U2 w; w.f4 = *(const float4*)&sm[OFF_W2 + (j0 + jj) * HID + k];
                    #pragma unroll
                    for (int u = 0; u < 4; u++) {
                        ffma2(acc[u][jj], g[u].u[0], w.u[0]);
                        ffma2(acc[u][jj], g[u].u[1], w.u[1]);
                    }
                }
            }
            #pragma unroll
            for (int u = 0; u < 4; u++) {
                int s = lane + 32 * u;
                float4 h0  = *(const float4*)&sm[OFF_H1 + s * RS + j0];
                float4 h1v = *(const float4*)&sm[OFF_H1 + s * RS + j0 + 4];
                float hh[8] = {h0.x, h0.y, h0.z, h0.w, h1v.x, h1v.y, h1v.z, h1v.w};
                float gf0 = 0.f, gf1 = 0.f, gf2 = 0.f, gf3 = 0.f;
                #pragma unroll
                for (int jj = 0; jj < 8; jj++) {
                    float lo, hi;
                    unpack2(acc[u][jj], lo, hi);
                    float a = lo + hi;
                    float g1v = a * (1.0f - hh[jj] * hh[jj]);
                    float4 w = *(const float4*)&sm[OFF_W1T + (j0 + jj) * 4];
                    gf0 = fmaf(g1v, w.x, gf0);
                    gf1 = fmaf(g1v, w.y, gf1);
                    gf2 = fmaf(g1v, w.z, gf2);
                    gf3 = fmaf(g1v, w.w, gf3);
                }
                pf[u][0] = gf0; pf[u][1] = gf1; pf[u][2] = gf2; pf[u][3] = gf3;
            }
        }
        __syncthreads();   // all G2 reads done -> PF may overlay G2

        {
            const int jg = tid >> 5;   // 16 j-groups
            #pragma unroll
            for (int u = 0; u < 4; u++)
                *(float4*)&sm[OFF_PF + (jg * 128 + lane + 32 * u) * 4]
                    = make_float4(pf[u][0], pf[u][1], pf[u][2], pf[u][3]);
        }
        __syncthreads();

        // ---- Reduce partials + analytic dynamics + output (shfl merge) ---
        {
            int rs = tid >> 2, c = tid & 3;      // 128 s x 4 comps
            float a = 0.f;
            #pragma unroll
            for (int jg = 0; jg < 16; jg++)
                a += sm[OFF_PF + (jg * 128 + rs) * 4 + c];
            float a1 = __shfl_down_sync(0xffffffffu, a, 1);
            float a2 = __shfl_down_sync(0xffffffffu, a, 2);
            float a3 = __shfl_down_sync(0xffffffffu, a, 3);

            if (c == 0) {
                const int s = rs;
                float gf0 = a, gf1 = a1, gf2 = a2, gf3 = a3;

                float w1 = sm[OFF_XD + s * 2 + 0];
                float w2 = sm[OFF_XD + s * 2 + 1];
                float s1 = sm[OFF_FT + s * 4 + 0];
                float c1 = sm[OFF_FT + s * 4 + 1];
                float s2 = sm[OFF_FT + s * 4 + 2];
                float c2 = sm[OFF_FT + s * 4 + 3];

                float sd = s1 * c2 - c1 * s2;      // sin(t1 - t2)
                float cd = c1 * c2 + s1 * s2;      // cos(t1 - t2)

                float dV1 = gf0 * c1 - gf1 * s1;
                float dV2 = gf2 * c2 - gf3 * s2;

                float tt  = w1 * w2 * sd;
                float dL1 = -tt - dV1;
                float dL2 =  tt - dV2;

                float cc = sd * (w2 - w1);
                float r1 = dL1 - w2 * cc;
                float r2 = dL2 - w1 * cc;

                float det  = 2.0f - cd * cd;
                float rdet = __fdividef(1.0f, det);
                float qdd1 = (r1 - cd * r2) * rdet;
                float qdd2 = (2.0f * r2 - cd * r1) * rdet;

                int gs = base + s;
                if (gs < B)
                    *(float4*)&out[gs * 4] = make_float4(w1, w2, qdd1, qdd2);
            }
        }
    }
}

extern "C" void kernel_launch(void* const* d_in, const int* in_sizes, int n_in,
                              void* d_out, int out_size)
{
    const float* X  = (const float*)d_in[0];
    const float* W1 = (const float*)d_in[1];
    const float* b1 = (const float*)d_in[2];
    const float* W2 = (const float*)d_in[3];
    const float* b2 = (const float*)d_in[4];
    const float* W3 = (const float*)d_in[5];
    // d_in[6] = b3: no effect on grad(V) -> unused
    float* out = (float*)d_out;

    int B = in_sizes[0] / 4;
    int ntiles = (B + TILE - 1) / TILE;

    int nsm = 148;
    cudaDeviceGetAttribute(&nsm, cudaDevAttrMultiProcessorCount, 0);
    int grid = ntiles < nsm ? ntiles : nsm;

    size_t smem = SMEM_FLOATS * sizeof(float);
    cudaFuncSetAttribute(lnn_kernel, cudaFuncAttributeMaxDynamicSharedMemorySize,
                         (int)smem);
    lnn_kernel<<<grid, NT, smem>>>(X, W1, b1, W2, b2, W3, out, B, ntiles);
}

// round 16
// speedup vs baseline: 1.7153x; 1.0024x over previous
#include <cuda_runtime.h>
#include <math.h>
#include <stdint.h>

#define NT   512
#define TILE 128
#define HID  128
#define RS   132   // lane-stride 132 floats -> 4-bank quads tile all 32 banks

// shared-memory float offsets
#define OFF_W2   0        // 16384  W2[j][k] row-major
#define OFF_H1   16384    // 16896  h1row[s][j] stride RS    -> ends 33280
#define OFF_G2   33280    // 16896  g2row[s][k] stride RS    -> ends 50176
#define OFF_W1T  50176    // 512    W1T[j][i]
#define OFF_B1   50688    // 128
#define OFF_B2   50816    // 128
#define OFF_W3   50944    // 128
#define OFF_FT0  51072    // 512    feat[s][4] parity 0
#define OFF_FT1  51584    // 512    feat[s][4] parity 1
#define OFF_XD0  52096    // 256    qd[s][2] parity 0
#define OFF_XD1  52352    // 256    qd[s][2] parity 1
#define OFF_XB   52608    // 512    X prefetch buffer [s][4]
#define OFF_PF   OFF_G2   // 8192   gfeat partials [jg][s][4] overlay G2 (dead)
#define SMEM_FLOATS 53120 // 212480 bytes

typedef unsigned long long ull;
union F4U2 { float4 f4; ull u[2]; };

__device__ __forceinline__ void ffma2(ull& acc, ull a, ull b) {
    asm("fma.rn.f32x2 %0, %1, %2, %0;" : "+l"(acc) : "l"(a), "l"(b));
}
__device__ __forceinline__ ull pack2(float lo, float hi) {
    ull r; asm("mov.b64 %0, {%1, %2};" : "=l"(r) : "f"(lo), "f"(hi)); return r;
}
__device__ __forceinline__ void unpack2(ull v, float& lo, float& hi) {
    asm("mov.b64 {%0, %1}, %2;" : "=f"(lo), "=f"(hi) : "l"(v));
}
__device__ __forceinline__ float tanh_hw(float x) {
    float r;
    asm("tanh.approx.f32 %0, %1;" : "=f"(r) : "f"(x));
    return r;
}
__device__ __forceinline__ uint32_t smem_u32(const void* p) {
    uint32_t a;
    asm("{ .reg .u64 t; cvta.to.shared.u64 t, %1; cvt.u32.u64 %0, t; }"
        : "=r"(a) : "l"(p));
    return a;
}
__device__ __forceinline__ void cp_async16(uint32_t dst, const void* src) {
    asm volatile("cp.async.ca.shared.global [%0], [%1], 16;"
                 :: "r"(dst), "l"(src) : "memory");
}

__global__ __launch_bounds__(NT, 1)
void lnn_kernel(const float* __restrict__ X,
                const float* __restrict__ W1, const float* __restrict__ b1,
                const float* __restrict__ W2, const float* __restrict__ b2,
                const float* __restrict__ W3,
                float* __restrict__ out, int B, int ntiles)
{
    extern __shared__ float sm[];
    const int tid  = threadIdx.x;
    const int lane = tid & 31;
    const uint32_t xb_addr = smem_u32(&sm[OFF_XB]);

    // ---------------- One-time staging: weights + first X -----------------
    {
        const float4* W2v = (const float4*)W2;
        for (int i = tid; i < HID * HID / 4; i += NT)
            *(float4*)&sm[OFF_W2 + i * 4] = W2v[i];
        if (tid < 4 * HID) {
            int r = tid >> 7, j = tid & 127;      // W1 is [4][128]
            sm[OFF_W1T + j * 4 + r] = W1[tid];
        }
        if (tid < HID) {
            sm[OFF_B1 + tid] = b1[tid];
            sm[OFF_B2 + tid] = b2[tid];
            sm[OFF_W3 + tid] = W3[tid];
        }
        if (tid >= 128 && tid < 256) {
            int s  = tid - 128;
            int gs = blockIdx.x * TILE + s;
            if (gs < B) cp_async16(xb_addr + s * 16, &X[gs * 4]);
            else        *(float4*)&sm[OFF_XB + s * 4] = make_float4(0.f, 0.f, 0.f, 0.f);
            asm volatile("cp.async.commit_group;");
            asm volatile("cp.async.wait_group 0;" ::: "memory");
        }
    }
    __syncthreads();

    // ---------------- First tile prologue: stage p=0 + Phase A ------------
    if (tid < 256) {
        int s = tid & 127;
        float4 x = *(const float4*)&sm[OFF_XB + s * 4];
        if (tid < 128) {
            float s1, c1;
            sincosf(x.x, &s1, &c1);
            sm[OFF_FT0 + s * 4 + 0] = s1;
            sm[OFF_FT0 + s * 4 + 1] = c1;
            sm[OFF_XD0 + s * 2 + 0] = x.z;
            sm[OFF_XD0 + s * 2 + 1] = x.w;
        } else {
            float s2, c2;
            sincosf(x.y, &s2, &c2);
            sm[OFF_FT0 + s * 4 + 2] = s2;
            sm[OFF_FT0 + s * 4 + 3] = c2;
        }
    }
    __syncthreads();
    {
        const int s  = tid & 127;
        const int j0 = (tid >> 7) * 32;
        float4 f = *(const float4*)&sm[OFF_FT0 + s * 4];
        #pragma unroll
        for (int c = 0; c < 32; c += 4) {
            float hv[4];
            #pragma unroll
            for (int q = 0; q < 4; q++) {
                int j = j0 + c + q;
                float4 w = *(const float4*)&sm[OFF_W1T + j * 4];
                float z = sm[OFF_B1 + j] + f.x*w.x + f.y*w.y + f.z*w.z + f.w*w.w;
                hv[q] = tanh_hw(z);
            }
            *(float4*)&sm[OFF_H1 + s * RS + j0 + c]
                = make_float4(hv[0], hv[1], hv[2], hv[3]);
        }
    }
    __syncthreads();

    const int og8 = (tid >> 5) * 8;    // warp-uniform output group (k0 / j0)
    int p = 0;

    // ---------------- Persistent loop (invariant: H1, FT(p), XD(p) ready) -
    for (int tile = blockIdx.x; tile < ntiles; tile += gridDim.x) {
        const int base = tile * TILE;
        const int tn   = tile + gridDim.x;
        const int oft  = p ? OFF_FT1 : OFF_FT0;
        const int oxd  = p ? OFF_XD1 : OFF_XD0;
        const int oftn = p ? OFF_FT0 : OFF_FT1;
        const int oxdn = p ? OFF_XD0 : OFF_XD1;

        // issue prefetch for next tile (same threads will wait in the tail)
        if (tn < ntiles && tid >= 128 && tid < 256) {
            int s  = tid - 128;
            int gs = tn * TILE + s;
            if (gs < B) cp_async16(xb_addr + s * 16, &X[gs * 4]);
            else        *(float4*)&sm[OFF_XB + s * 4] = make_float4(0.f, 0.f, 0.f, 0.f);
            asm volatile("cp.async.commit_group;");
        }

        // ---- Phase B: z2 = h1@W2 (+b2); g2 = W3*sech^2 ----
        {
            const int k0 = og8;
            ull acc[4][4];
            #pragma unroll
            for (int m = 0; m < 4; m++) {
                ull bp = pack2(sm[OFF_B2 + k0 + 2*m], sm[OFF_B2 + k0 + 2*m + 1]);
                acc[0][m] = bp; acc[1][m] = bp; acc[2][m] = bp; acc[3][m] = bp;
            }
            #pragma unroll 4
            for (int j = 0; j < HID; j += 4) {
                float hv[4][4];
                #pragma unroll
                for (int u = 0; u < 4; u++) {
                    float4 h = *(const float4*)&sm[OFF_H1 + (lane + 32 * u) * RS + j];
                    hv[u][0] = h.x; hv[u][1] = h.y; hv[u][2] = h.z; hv[u][3] = h.w;
                }
                #pragma unroll
                for (int q = 0; q < 4; q++) {
                    F4U2 wlo, whi;
                    wlo.f4 = *(const float4*)&sm[OFF_W2 + (j + q) * HID + k0];
                    whi.f4 = *(const float4*)&sm[OFF_W2 + (j + q) * HID + k0 + 4];
                    #pragma unroll
                    for (int u = 0; u < 4; u++) {
                        ull hp = pack2(hv[u][q], hv[u][q]);
                        ffma2(acc[u][0], hp, wlo.u[0]);
                        ffma2(acc[u][1], hp, wlo.u[1]);
                        ffma2(acc[u][2], hp, whi.u[0]);
                        ffma2(acc[u][3], hp, whi.u[1]);
                    }
                }
            }
            #pragma unroll
            for (int u = 0; u < 4; u++) {
                int s = lane + 32 * u;
                float g[8];
                #pragma unroll
                for (int m = 0; m < 4; m++) {
                    float z0, z1;
                    unpack2(acc[u][m], z0, z1);
                    float t0 = tanh_hw(z0), t1 = tanh_hw(z1);
                    g[2*m]     = sm[OFF_W3 + k0 + 2*m]     * (1.0f - t0 * t0);
                    g[2*m + 1] = sm[OFF_W3 + k0 + 2*m + 1] * (1.0f - t1 * t1);
                }
                *(float4*)&sm[OFF_G2 + s * RS + k0]     = make_float4(g[0], g[1], g[2], g[3]);
                *(float4*)&sm[OFF_G2 + s * RS + k0 + 4] = make_float4(g[4], g[5], g[6], g[7]);
            }
        }
        __syncthreads();

        // ---- Phase C: a = g2@W2^T (k-dot); g1; gfeat partials ----
        float pf[4][4];
        {
            const int j0 = og8;
            ull acc[4][8];
            #pragma unroll
            for (int u = 0; u < 4; u++)
                #pragma unroll
                for (int jj = 0; jj < 8; jj++) acc[u][jj] = 0ull;

            #pragma unroll 2
            for (int k = 0; k < HID; k += 4) {
                F4U2 g[4];
                #pragma unroll
                for (int u = 0; u < 4; u++)
                    g[u].f4 = *(const float4*)&sm[OFF_G2 + (lane + 32 * u) * RS + k];
                #pragma unroll
                for (int jj = 0; jj < 8; jj++) {
                    F4U2 w; w.f4 = *(const float4*)&sm[OFF_W2 + (j0 + jj) * HID + k];
                    #pragma unroll
                    for (int u = 0; u < 4; u++) {
                        ffma2(acc[u][jj], g[u].u[0], w.u[0]);
                        ffma2(acc[u][jj], g[u].u[1], w.u[1]);
                    }
                }
            }
            #pragma unroll
            for (int u = 0; u < 4; u++) {
                int s = lane + 32 * u;
                float4 h0  = *(const float4*)&sm[OFF_H1 + s * RS + j0];
                float4 h1v = *(const float4*)&sm[OFF_H1 + s * RS + j0 + 4];
                float hh[8] = {h0.x, h0.y, h0.z, h0.w, h1v.x, h1v.y, h1v.z, h1v.w};
                float gf0 = 0.f, gf1 = 0.f, gf2 = 0.f, gf3 = 0.f;
                #pragma unroll
                for (int jj = 0; jj < 8; jj++) {
                    float lo, hi;
                    unpack2(acc[u][jj], lo, hi);
                    float a = lo + hi;
                    float g1v = a * (1.0f - hh[jj] * hh[jj]);
                    float4 w = *(const float4*)&sm[OFF_W1T + (j0 + jj) * 4];
                    gf0 = fmaf(g1v, w.x, gf0);
                    gf1 = fmaf(g1v, w.y, gf1);
                    gf2 = fmaf(g1v, w.z, gf2);
                    gf3 = fmaf(g1v, w.w, gf3);
                }
                pf[u][0] = gf0; pf[u][1] = gf1; pf[u][2] = gf2; pf[u][3] = gf3;
            }
        }
        __syncthreads();   // all G2 reads done -> PF may overlay G2

        {
            const int jg = tid >> 5;   // 16 j-groups
            #pragma unroll
            for (int u = 0; u < 4; u++)
                *(float4*)&sm[OFF_PF + (jg * 128 + lane + 32 * u) * 4]
                    = make_float4(pf[u][0], pf[u][1], pf[u][2], pf[u][3]);
        }
        __syncthreads();

        // ---- Tail split: epilogue(T) || staging + Phase A(T+1) ----
        if (tid < 128) {
            // reduce PF + analytic dynamics + output for sample s = tid
            const int s = tid;
            float gf0 = 0.f, gf1 = 0.f, gf2 = 0.f, gf3 = 0.f;
            #pragma unroll
            for (int jg = 0; jg < 16; jg++) {
                float4 q = *(const float4*)&sm[OFF_PF + (jg * 128 + s) * 4];
                gf0 += q.x; gf1 += q.y; gf2 += q.z; gf3 += q.w;
            }

            float w1 = sm[oxd + s * 2 + 0];
            float w2 = sm[oxd + s * 2 + 1];
            float s1 = sm[oft + s * 4 + 0];
            float c1 = sm[oft + s * 4 + 1];
            float s2 = sm[oft + s * 4 + 2];
            float c2 = sm[oft + s * 4 + 3];

            float sd = s1 * c2 - c1 * s2;      // sin(t1 - t2)
            float cd = c1 * c2 + s1 * s2;      // cos(t1 - t2)

            float dV1 = gf0 * c1 - gf1 * s1;
            float dV2 = gf2 * c2 - gf3 * s2;

            float tt  = w1 * w2 * sd;
            float dL1 = -tt - dV1;
            float dL2 =  tt - dV2;

            float cc = sd * (w2 - w1);
            float r1 = dL1 - w2 * cc;
            float r2 = dL2 - w1 * cc;

            float det  = 2.0f - cd * cd;
            float rdet = __fdividef(1.0f, det);
            float qdd1 = (r1 - cd * r2) * rdet;
            float qdd2 = (2.0f * r2 - cd * r1) * rdet;

            int gs = base + s;
            if (gs < B)
                *(float4*)&out[gs * 4] = make_float4(w1, w2, qdd1, qdd2);
        } else if (tn < ntiles) {
            if (tid < 256)
                asm volatile("cp.async.wait_group 0;" ::: "memory");
            asm volatile("bar.sync 3, 384;" ::: "memory");
            if (tid < 384) {
                int s = (tid - 128) & 127;
                float4 x = *(const float4*)&sm[OFF_XB + s * 4];
                if (tid < 256) {
                    float s1, c1;
                    sincosf(x.x, &s1, &c1);
                    sm[oftn + s * 4 + 0] = s1;
                    sm[oftn + s * 4 + 1] = c1;
                    sm[oxdn + s * 2 + 0] = x.z;
                    sm[oxdn + s * 2 + 1] = x.w;
                } else {
                    float s2, c2;
                    sincosf(x.y, &s2, &c2);
                    sm[oftn + s * 4 + 2] = s2;
                    sm[oftn + s * 4 + 3] = c2;
                }
            }
            asm volatile("bar.sync 3, 384;" ::: "memory");
            // Phase A(T+1) on 256 threads (tid 128-383), 64 j each
            if (tid < 384) {
                const int s  = (tid - 128) & 127;
                const int j0 = (tid < 256) ? 64 : 0;
                float4 f = *(const float4*)&sm[oftn + s * 4];
                #pragma unroll 4
                for (int c = 0; c < 64; c += 4) {
                    float hv[4];
                    #pragma unroll
                    for (int q = 0; q < 4; q++) {
                        int j = j0 + c + q;
                        float4 w = *(const float4*)&sm[OFF_W1T + j * 4];
                        float z = sm[OFF_B1 + j] + f.x*w.x + f.y*w.y + f.z*w.z + f.w*w.w;
                        hv[q] = tanh_hw(z);
                    }
                    *(float4*)&sm[OFF_H1 + s * RS + j0 + c]
                        = make_float4(hv[0], hv[1], hv[2], hv[3]);
                }
            }
        }
        __syncthreads();   // join: H1(T+1), FT/XD(p^1) ready; XBUF free
        p ^= 1;
    }
}

extern "C" void kernel_launch(void* const* d_in, const int* in_sizes, int n_in,
                              void* d_out, int out_size)
{
    const float* X  = (const float*)d_in[0];
    const float* W1 = (const float*)d_in[1];
    const float* b1 = (const float*)d_in[2];
    const float* W2 = (const float*)d_in[3];
    const float* b2 = (const float*)d_in[4];
    const float* W3 = (const float*)d_in[5];
    // d_in[6] = b3: no effect on grad(V) -> unused
    float* out = (float*)d_out;

    int B = in_sizes[0] / 4;
    int ntiles = (B + TILE - 1) / TILE;

    int nsm = 148;
    cudaDeviceGetAttribute(&nsm, cudaDevAttrMultiProcessorCount, 0);
    int grid = ntiles < nsm ? ntiles : nsm;

    size_t smem = SMEM_FLOATS * sizeof(float);
    cudaFuncSetAttribute(lnn_kernel, cudaFuncAttributeMaxDynamicSharedMemorySize,
                         (int)smem);
    lnn_kernel<<<grid, NT, smem>>>(X, W1, b1, W2, b2, W3, out, B, ntiles);
}